// round 1
// baseline (speedup 1.0000x reference)
#include <cuda_runtime.h>

// Problem shape (fixed by reference setup_inputs)
#define BB 128
#define AA 1024
#define MM 6
#define TT 16
#define THREADS 256
#define AGENTS_PER_THREAD (AA / THREADS)   // 4
#define NWARPS (THREADS / 32)              // 8

#define AGENT_THRESH 0.5f
#define X_DIS_THRESH 1.5f
#define Y_DIS_THRESH 3.0f
#define DIS_THRESH_SQ 9.0f                 // dist > 3  <=>  dx*dx+dy*dy > 9
#define MEAN_SCALE (1.0f / (float)(BB * TT * 2))   // mean over [B,T,2]

__global__ void zero_out_kernel(float* out) { out[0] = 0.0f; }

__global__ __launch_bounds__(THREADS)
void plan_pred_collision_loss_kernel(
    const float* __restrict__ ego_plan,   // [B, T, 2]
    const float* __restrict__ preds,      // [B, A, M, T, 2]
    const float* __restrict__ scores,     // [B, A, M]
    const float* __restrict__ pmask,      // [B, T]
    float* __restrict__ out)              // scalar
{
    const int b   = blockIdx.x;
    const int tid = threadIdx.x;
    const int wid = tid >> 5;
    const int lane = tid & 31;

    __shared__ float s_ego[TT * 2];
    __shared__ float s_pmask[TT];
    __shared__ float s_xw[NWARPS][TT];
    __shared__ float s_yw[NWARPS][TT];

    if (tid < TT * 2) s_ego[tid] = ego_plan[b * TT * 2 + tid];
    if (tid < TT)     s_pmask[tid] = pmask[b * TT + tid];
    __syncthreads();

    float xmin[TT], ymin[TT];
#pragma unroll
    for (int t = 0; t < TT; t++) { xmin[t] = 1e30f; ymin[t] = 1e30f; }

#pragma unroll
    for (int i = 0; i < AGENTS_PER_THREAD; i++) {
        const int a = tid + i * THREADS;

        // ---- argmax over modes (first-max wins, like jnp.argmax) ----
        const float* sc = scores + ((size_t)b * AA + a) * MM;
        float best = __ldg(&sc[0]);
        int   bm   = 0;
#pragma unroll
        for (int m = 1; m < MM; m++) {
            float v = __ldg(&sc[m]);
            if (v > best) { best = v; bm = m; }
        }
        const float conf_pen = (best < AGENT_THRESH) ? 100.0f : 0.0f;

        // ---- gather best-mode trajectory: contiguous 128B, 128B-aligned ----
        const float4* traj =
            (const float4*)(preds + (((size_t)b * AA + a) * MM + bm) * (TT * 2));

#pragma unroll
        for (int q = 0; q < TT / 2; q++) {          // 8 x float4 = 16 (x,y) points
            const float4 v = __ldg(&traj[q]);
            const int t0 = q * 2;
            // point t0
            {
                float dx = s_ego[t0 * 2 + 0] - v.x;
                float dy = s_ego[t0 * 2 + 1] - v.y;
                float pen = (dx * dx + dy * dy > DIS_THRESH_SQ) ? 100.0f : conf_pen;
                xmin[t0] = fminf(xmin[t0], fabsf(dx) + pen);
                ymin[t0] = fminf(ymin[t0], fabsf(dy) + pen);
            }
            // point t0+1
            {
                float dx = s_ego[(t0 + 1) * 2 + 0] - v.z;
                float dy = s_ego[(t0 + 1) * 2 + 1] - v.w;
                float pen = (dx * dx + dy * dy > DIS_THRESH_SQ) ? 100.0f : conf_pen;
                xmin[t0 + 1] = fminf(xmin[t0 + 1], fabsf(dx) + pen);
                ymin[t0 + 1] = fminf(ymin[t0 + 1], fabsf(dy) + pen);
            }
        }
    }

    // ---- intra-warp min reduction over the 32 lanes, all 16 timesteps ----
#pragma unroll
    for (int t = 0; t < TT; t++) {
#pragma unroll
        for (int o = 16; o > 0; o >>= 1) {
            xmin[t] = fminf(xmin[t], __shfl_xor_sync(0xffffffffu, xmin[t], o));
            ymin[t] = fminf(ymin[t], __shfl_xor_sync(0xffffffffu, ymin[t], o));
        }
    }
    if (lane == 0) {
#pragma unroll
        for (int t = 0; t < TT; t++) { s_xw[wid][t] = xmin[t]; s_yw[wid][t] = ymin[t]; }
    }
    __syncthreads();

    // ---- cross-warp min + loss transform + block sum (warp 0) ----
    if (tid < 32) {
        float contrib = 0.0f;
        if (lane < TT) {
            float xm = s_xw[0][lane];
            float ym = s_yw[0][lane];
#pragma unroll
            for (int w = 1; w < NWARPS; w++) {
                xm = fminf(xm, s_xw[w][lane]);
                ym = fminf(ym, s_yw[w][lane]);
            }
            float xl = (xm <= X_DIS_THRESH) ? (X_DIS_THRESH - xm) : 0.0f;
            float yl = (ym <= Y_DIS_THRESH) ? (Y_DIS_THRESH - ym) : 0.0f;
            contrib = (xl + yl) * s_pmask[lane];
        }
#pragma unroll
        for (int o = 16; o > 0; o >>= 1)
            contrib += __shfl_xor_sync(0xffffffffu, contrib, o);
        if (lane == 0)
            atomicAdd(out, contrib * MEAN_SCALE);
    }
}

extern "C" void kernel_launch(void* const* d_in, const int* in_sizes, int n_in,
                              void* d_out, int out_size)
{
    const float* ego_plan = (const float*)d_in[0];  // [B,T,2]
    const float* preds    = (const float*)d_in[1];  // [B,A,M,T,2]
    const float* scores   = (const float*)d_in[2];  // [B,A,M]
    const float* pmask    = (const float*)d_in[3];  // [B,T]
    float* out = (float*)d_out;

    zero_out_kernel<<<1, 1>>>(out);
    plan_pred_collision_loss_kernel<<<BB, THREADS>>>(ego_plan, preds, scores, pmask, out);
}